// round 3
// baseline (speedup 1.0000x reference)
#include <cuda_runtime.h>
#include <cuda_fp16.h>
#include <cstdint>

// ============================================================
// out[B*S, O] = fakequant(x)[B*S, I] @ dequant(W)[O, I]^T + bias
// M=8192, N=4096, K=4096
// NOTE: harness compiles for plain sm_100 (no 'a') -> no tcgen05.
// Use mma.sync (HMMA) + ldmatrix + cp.async, all baseline PTX.
// ============================================================
#define M_TOTAL 8192
#define N_TOTAL 4096
#define K_TOTAL 4096
#define SEQ     2048
#define NGRP    32

__device__ __align__(256) __half g_xq[(size_t)M_TOTAL * K_TOTAL];  // 67 MB
__device__ __align__(256) __half g_w [(size_t)N_TOTAL * K_TOTAL];  // 33.5 MB

__device__ __forceinline__ uint32_t smem_u32(const void* p) {
    uint32_t a;
    asm("{ .reg .u64 t; cvta.to.shared.u64 t, %1; cvt.u32.u64 %0, t; }" : "=r"(a) : "l"(p));
    return a;
}

#define CP_ASYNC_16(dst, src) \
    asm volatile("cp.async.cg.shared.global.L2::128B [%0], [%1], 16;" \
                 :: "r"(dst), "l"(src) : "memory")
#define CP_ASYNC_COMMIT() asm volatile("cp.async.commit_group;" ::: "memory")
#define CP_ASYNC_WAIT(n)  asm volatile("cp.async.wait_group %0;" :: "n"(n) : "memory")

__device__ __forceinline__ void ldmatrix_x4(uint32_t& r0, uint32_t& r1,
                                            uint32_t& r2, uint32_t& r3, uint32_t addr) {
    asm volatile("ldmatrix.sync.aligned.m8n8.x4.shared.b16 {%0,%1,%2,%3}, [%4];"
                 : "=r"(r0), "=r"(r1), "=r"(r2), "=r"(r3) : "r"(addr));
}

__device__ __forceinline__ void mma_m16n8k16(float& c0, float& c1, float& c2, float& c3,
                                             uint32_t a0, uint32_t a1, uint32_t a2, uint32_t a3,
                                             uint32_t b0, uint32_t b1) {
    asm volatile(
        "mma.sync.aligned.m16n8k16.row.col.f32.f16.f16.f32 "
        "{%0,%1,%2,%3}, {%4,%5,%6,%7}, {%8,%9}, {%0,%1,%2,%3};"
        : "+f"(c0), "+f"(c1), "+f"(c2), "+f"(c3)
        : "r"(a0), "r"(a1), "r"(a2), "r"(a3), "r"(b0), "r"(b1));
}

// ============================================================
// Kernel 1: activation fake-quant -> fp16
// x_q = clip(rint(x/s), -127, 127) * s  (rintf = round-half-even = jnp.round)
// ============================================================
__global__ void __launch_bounds__(256) quant_x_kernel(const float* __restrict__ x,
                                                      const float* __restrict__ ascale) {
    int idx = blockIdx.x * 256 + threadIdx.x;              // one float4 per thread
    float4 v = ((const float4*)x)[idx];
    float s = ascale[(idx >> 10) & (SEQ - 1)];             // row = idx>>10 (1024 float4/row)
    float a = fminf(fmaxf(rintf(__fdiv_rn(v.x, s)), -127.f), 127.f) * s;
    float b = fminf(fmaxf(rintf(__fdiv_rn(v.y, s)), -127.f), 127.f) * s;
    float c = fminf(fmaxf(rintf(__fdiv_rn(v.z, s)), -127.f), 127.f) * s;
    float d = fminf(fmaxf(rintf(__fdiv_rn(v.w, s)), -127.f), 127.f) * s;
    __half2 h0 = __floats2half2_rn(a, b);
    __half2 h1 = __floats2half2_rn(c, d);
    uint2 packed;
    packed.x = *(uint32_t*)&h0;
    packed.y = *(uint32_t*)&h1;
    ((uint2*)g_xq)[idx] = packed;
}

// ============================================================
// Kernel 2: int4 weight dequant -> fp16, K-major [O][I]
// ============================================================
__global__ void __launch_bounds__(256) dequant_w_kernel(const int* __restrict__ qw,
                                                        const float* __restrict__ ws,
                                                        const int* __restrict__ wz) {
    int idx = blockIdx.x * 256 + threadIdx.x;  // 4 packed int32 -> 8 halves
    int4 q = ((const int4*)qw)[idx];
    int j0 = idx << 2;                         // flat int32 index = o*2048 + j
    int o = j0 >> 11;
    int g = (j0 & 2047) >> 6;                  // group = j/64 (const over 4 consecutive j)
    float sc = ws[o * NGRP + g];
    float z  = (float)wz[o * NGRP + g];
    int qs[4] = {q.x, q.y, q.z, q.w};
    __half2 h[4];
#pragma unroll
    for (int t = 0; t < 4; t++) {
        float lo = ((float)(qs[t] & 15) - z) * sc;
        float hi = ((float)((qs[t] >> 4) & 15) - z) * sc;
        h[t] = __floats2half2_rn(lo, hi);
    }
    uint4 packed;
    packed.x = *(uint32_t*)&h[0];
    packed.y = *(uint32_t*)&h[1];
    packed.z = *(uint32_t*)&h[2];
    packed.w = *(uint32_t*)&h[3];
    ((uint4*)g_w)[idx] = packed;
}

// ============================================================
// Kernel 3: HMMA GEMM. Block 128x128, BK=64, 3-stage cp.async,
// 8 warps (4 M x 2 N), warp tile 32x64, m16n8k16 fragments.
// ============================================================
#define BM 128
#define BN 128
#define BK 64
#define STAGES 3
#define NT (K_TOTAL / BK)          // 64

#define TILE_BYTES (BM * BK * 2)   // 16384 per operand per stage
#define STAGE_BYTES (2 * TILE_BYTES)
#define SM_TOTAL (STAGES * STAGE_BYTES)   // 96 KB

// swizzle within a 128B row (BK=64 halves): XOR chunk bits [4:6] with row bits [7:9]
__device__ __forceinline__ uint32_t swz(uint32_t off) {
    return off ^ ((off >> 3) & 0x70);
}

__global__ void __launch_bounds__(256, 1) gemm_kernel(const float* __restrict__ bias,
                                                      float* __restrict__ out) {
    extern __shared__ char smem[];
    const uint32_t sb = smem_u32(smem);
    const int tid  = threadIdx.x;
    const int lane = tid & 31;
    const int wid  = tid >> 5;
    const int warp_m = wid >> 1;           // 0..3  -> 32 rows
    const int warp_n = wid & 1;            // 0..1  -> 64 cols
    const int m0 = blockIdx.y * BM;
    const int n0 = blockIdx.x * BN;

    // ---- global load addressing (4 chunks A + 4 chunks B per thread per stage)
    const int ld_row = tid >> 3;           // 0..31, step 32 per it
    const int ld_ch  = tid & 7;            // 16B chunk in row
    const __half* Agp = g_xq + (size_t)(m0 + ld_row) * K_TOTAL + ld_ch * 8;
    const __half* Bgp = g_w  + (size_t)(n0 + ld_row) * K_TOTAL + ld_ch * 8;
    const uint32_t ld_soff = swz((ld_row << 7) + (ld_ch << 4));

    // ---- ldmatrix lane addressing
    // A x4: m0=(r0..7,k0..7) m1=(r8..15,k0..7) m2=(r0..7,k8..15) m3=(r8..15,k8..15)
    const int a_row  = warp_m * 32 + ((lane >> 3) & 1) * 8 + (lane & 7);
    const int a_kofb = ((lane >> 4) & 1) * 16;  // bytes
    // B x4: m0=(n0..7,k0..7) m1=(n0..7,k8..15) m2=(n8..15,k0..7) m3=(n8..15,k8..15)
    const int b_row  = warp_n * 64 + ((lane >> 4) & 1) * 8 + (lane & 7);
    const int b_kofb = ((lane >> 3) & 1) * 16;

    float c[2][8][4];
#pragma unroll
    for (int mt = 0; mt < 2; mt++)
#pragma unroll
        for (int nt = 0; nt < 8; nt++)
#pragma unroll
            for (int j = 0; j < 4; j++) c[mt][nt][j] = 0.f;

    auto load_stage = [&](int kt, int stage) {
        uint32_t sa = sb + stage * STAGE_BYTES + ld_soff;
        uint32_t sbB = sa + TILE_BYTES;
        const __half* ag = Agp + kt * BK;
        const __half* bg = Bgp + kt * BK;
#pragma unroll
        for (int it = 0; it < 4; it++) {
            CP_ASYNC_16(sa  + it * (32 << 7), ag + (size_t)(it * 32) * K_TOTAL);
            CP_ASYNC_16(sbB + it * (32 << 7), bg + (size_t)(it * 32) * K_TOTAL);
        }
    };

    // prologue
#pragma unroll
    for (int s = 0; s < STAGES - 1; s++) {
        load_stage(s, s);
        CP_ASYNC_COMMIT();
    }

    int comp_stage = 0;  // kt % STAGES without division
    int load_stage_idx = STAGES - 1;

    for (int kt = 0; kt < NT; kt++) {
        CP_ASYNC_WAIT(STAGES - 2);
        __syncthreads();

        if (kt + STAGES - 1 < NT)
            load_stage(kt + STAGES - 1, load_stage_idx);
        CP_ASYNC_COMMIT();
        if (++load_stage_idx == STAGES) load_stage_idx = 0;

        const uint32_t Abase = sb + comp_stage * STAGE_BYTES;
        const uint32_t Bbase = Abase + TILE_BYTES;
        if (++comp_stage == STAGES) comp_stage = 0;

#pragma unroll
        for (int ks = 0; ks < 4; ks++) {
            uint32_t a[2][4];
#pragma unroll
            for (int mt = 0; mt < 2; mt++) {
                uint32_t addr = Abase + swz((uint32_t)(a_row + mt * 16) * 128 + ks * 32 + a_kofb);
                ldmatrix_x4(a[mt][0], a[mt][1], a[mt][2], a[mt][3], addr);
            }
            uint32_t b[8][2];
#pragma unroll
            for (int np = 0; np < 4; np++) {
                uint32_t addr = Bbase + swz((uint32_t)(b_row + np * 16) * 128 + ks * 32 + b_kofb);
                uint32_t r0, r1, r2, r3;
                ldmatrix_x4(r0, r1, r2, r3, addr);
                b[2 * np][0] = r0; b[2 * np][1] = r1;
                b[2 * np + 1][0] = r2; b[2 * np + 1][1] = r3;
            }
#pragma unroll
            for (int mt = 0; mt < 2; mt++)
#pragma unroll
                for (int nt = 0; nt < 8; nt++)
                    mma_m16n8k16(c[mt][nt][0], c[mt][nt][1], c[mt][nt][2], c[mt][nt][3],
                                 a[mt][0], a[mt][1], a[mt][2], a[mt][3],
                                 b[nt][0], b[nt][1]);
        }
    }

    // ---- epilogue: bias + store
    const int col_base = n0 + warp_n * 64 + (lane & 3) * 2;
    const int row_base = m0 + warp_m * 32 + (lane >> 2);
#pragma unroll
    for (int nt = 0; nt < 8; nt++) {
        const int col = col_base + nt * 8;
        const float2 bv = *(const float2*)(bias + col);
#pragma unroll
        for (int mt = 0; mt < 2; mt++) {
            const int r0 = row_base + mt * 16;
            float2 v0 = make_float2(c[mt][nt][0] + bv.x, c[mt][nt][1] + bv.y);
            float2 v1 = make_float2(c[mt][nt][2] + bv.x, c[mt][nt][3] + bv.y);
            *(float2*)(out + (size_t)r0 * N_TOTAL + col) = v0;
            *(float2*)(out + (size_t)(r0 + 8) * N_TOTAL + col) = v1;
        }
    }
}

// ============================================================
// launch
// ============================================================
extern "C" void kernel_launch(void* const* d_in, const int* in_sizes, int n_in,
                              void* d_out, int out_size) {
    const float* x       = (const float*)d_in[0];   // (4, 2048, 4096) f32
    const int*   qweight = (const int*)d_in[1];     // (4096, 2048) i32
    const float* ascale  = (const float*)d_in[2];   // (1, 2048, 1) f32
    const float* wscale  = (const float*)d_in[3];   // (4096, 32) f32
    const int*   wzero   = (const int*)d_in[4];     // (4096, 32) i32
    const float* bias    = (const float*)d_in[5];   // (4096,) f32
    float* out = (float*)d_out;                     // (4, 2048, 4096) f32

    cudaFuncSetAttribute(gemm_kernel, cudaFuncAttributeMaxDynamicSharedMemorySize, SM_TOTAL);

    quant_x_kernel<<<(M_TOTAL * K_TOTAL / 4) / 256, 256>>>(x, ascale);
    dequant_w_kernel<<<(N_TOTAL * K_TOTAL / 8) / 256, 256>>>(qweight, wscale, wzero);
    gemm_kernel<<<dim3(N_TOTAL / BN, M_TOTAL / BM), 256, SM_TOTAL>>>(bias, out);
}

// round 5
// speedup vs baseline: 1.3005x; 1.3005x over previous
#include <cuda_runtime.h>
#include <cuda_fp16.h>
#include <cstdint>

// ============================================================
// out[B*S, O] = fakequant(x) @ dequant(W)^T + bias
// M=8192, N=4096, K=4096, group G=128 (NGRP=32 groups)
//
// Exact-int8 formulation:
//   q_x = clip(rint(x/s_m), +-127)            (s8, exact)
//   w_c = nibble - zero[o,g]  in [-15,15]     (s8, exact, centered at prep)
//   out[m,o] = s_m * sum_g scale[o,g] * (sum_{i in g} q_x[m,i]*w_c[o,i]) + bias[o]
// GEMM core is integer (IMMA m16n8k32.s8), rescale fp32 per group.
// Target is plain sm_100 (no tcgen05) -> mma.sync + ldmatrix + cp.async.
// ============================================================
#define M_TOTAL 8192
#define N_TOTAL 4096
#define K_TOTAL 4096
#define SEQ     2048
#define NGRP    32

__device__ __align__(256) int8_t g_xq  [(size_t)M_TOTAL * K_TOTAL];  // 33.5 MB
__device__ __align__(256) int8_t g_w   [(size_t)N_TOTAL * K_TOTAL];  // 16.8 MB
__device__ __align__(256) float  g_wsT [NGRP * N_TOTAL];             // scale, group-major

__device__ __forceinline__ uint32_t smem_u32(const void* p) {
    uint32_t a;
    asm("{ .reg .u64 t; cvta.to.shared.u64 t, %1; cvt.u32.u64 %0, t; }" : "=r"(a) : "l"(p));
    return a;
}

#define CP_ASYNC_16(dst, src) \
    asm volatile("cp.async.cg.shared.global.L2::128B [%0], [%1], 16;" \
                 :: "r"(dst), "l"(src) : "memory")
#define CP_ASYNC_COMMIT() asm volatile("cp.async.commit_group;" ::: "memory")
#define CP_ASYNC_WAIT(n)  asm volatile("cp.async.wait_group %0;" :: "n"(n) : "memory")

__device__ __forceinline__ void ldmatrix_x4(uint32_t& r0, uint32_t& r1,
                                            uint32_t& r2, uint32_t& r3, uint32_t addr) {
    asm volatile("ldmatrix.sync.aligned.m8n8.x4.shared.b16 {%0,%1,%2,%3}, [%4];"
                 : "=r"(r0), "=r"(r1), "=r"(r2), "=r"(r3) : "r"(addr));
}

__device__ __forceinline__ void mma_s8(int& c0, int& c1, int& c2, int& c3,
                                       uint32_t a0, uint32_t a1, uint32_t a2, uint32_t a3,
                                       uint32_t b0, uint32_t b1) {
    asm volatile(
        "mma.sync.aligned.m16n8k32.row.col.s32.s8.s8.s32 "
        "{%0,%1,%2,%3}, {%4,%5,%6,%7}, {%8,%9}, {%0,%1,%2,%3};"
        : "+r"(c0), "+r"(c1), "+r"(c2), "+r"(c3)
        : "r"(a0), "r"(a1), "r"(a2), "r"(a3), "r"(b0), "r"(b1));
}

// ============================================================
// Kernel 1: activation quant -> s8 (rintf = round-half-even = jnp.round)
// ============================================================
__global__ void __launch_bounds__(256) quant_x_kernel(const float* __restrict__ x,
                                                      const float* __restrict__ ascale) {
    int idx = blockIdx.x * 256 + threadIdx.x;              // one float4 -> 4 s8
    float4 v = ((const float4*)x)[idx];
    float s = ascale[(idx >> 10) & (SEQ - 1)];             // row = idx>>10
    int qa = (int)fminf(fmaxf(rintf(__fdiv_rn(v.x, s)), -127.f), 127.f);
    int qb = (int)fminf(fmaxf(rintf(__fdiv_rn(v.y, s)), -127.f), 127.f);
    int qc = (int)fminf(fmaxf(rintf(__fdiv_rn(v.z, s)), -127.f), 127.f);
    int qd = (int)fminf(fmaxf(rintf(__fdiv_rn(v.w, s)), -127.f), 127.f);
    uint32_t packed = (qa & 0xFF) | ((qb & 0xFF) << 8) | ((qc & 0xFF) << 16) | ((qd & 0xFF) << 24);
    ((uint32_t*)g_xq)[idx] = packed;
}

// ============================================================
// Kernel 2: weight unpack + center -> s8, K-major [O][K]
// each int32 holds 2 nibbles: k=2j (low), k=2j+1 (high)
// ============================================================
__global__ void __launch_bounds__(256) prep_w_kernel(const int* __restrict__ qw,
                                                     const int* __restrict__ wz) {
    int idx = blockIdx.x * 256 + threadIdx.x;  // 4 int32 -> 8 s8
    int4 q = ((const int4*)qw)[idx];
    int j0 = idx << 2;                         // int32 index = o*2048 + j
    int o = j0 >> 11;
    int g = (j0 & 2047) >> 6;                  // group = j/64 (const over the 4 j's)
    int z = wz[o * NGRP + g];
    int qs[4] = {q.x, q.y, q.z, q.w};
    uint32_t out2[2];
    uint8_t* ob = (uint8_t*)out2;
#pragma unroll
    for (int t = 0; t < 4; t++) {
        int lo = (qs[t] & 15) - z;
        int hi = ((qs[t] >> 4) & 15) - z;
        ob[2 * t]     = (uint8_t)(int8_t)lo;
        ob[2 * t + 1] = (uint8_t)(int8_t)hi;
    }
    ((uint2*)g_w)[idx] = make_uint2(out2[0], out2[1]);
}

// ============================================================
// Kernel 3: transpose weight_scale [O][NGRP] -> [NGRP][O]
// ============================================================
__global__ void __launch_bounds__(256) transpose_ws_kernel(const float* __restrict__ ws) {
    int idx = blockIdx.x * 256 + threadIdx.x;  // over N_TOTAL*NGRP
    int o = idx >> 5, g = idx & 31;
    g_wsT[g * N_TOTAL + o] = ws[idx];
}

// ============================================================
// Kernel 4: IMMA GEMM. Block 128x128, BK=128 (= one group), 3-stage
// cp.async, 8 warps (4M x 2N), warp tile 32x64, m16n8k32.s8.
// Per-group fp32 rescale with per-column scale from smem.
// ============================================================
#define BM 128
#define BN 128
#define BK 128
#define STAGES 3
#define NT (K_TOTAL / BK)          // 32

#define TILE_BYTES (BM * BK)       // 16384 (int8)
#define STAGE_BYTES (2 * TILE_BYTES)
#define SM_MAIN  (STAGES * STAGE_BYTES)      // 96 KB
#define SM_SCL   SM_MAIN                     // scale_s[2][128] floats
#define SM_BIAS  (SM_SCL + 2 * 128 * 4)      // bias_s[128]
#define SM_ASC   (SM_BIAS + 128 * 4)         // ascale_s[128]
#define SM_TOTAL (SM_ASC + 128 * 4)

// SW128 swizzle on 128B rows
__device__ __forceinline__ uint32_t swz(uint32_t off) {
    return off ^ ((off >> 3) & 0x70);
}

__global__ void __launch_bounds__(256, 1) gemm_kernel(const float* __restrict__ bias,
                                                      const float* __restrict__ ascale,
                                                      float* __restrict__ out) {
    extern __shared__ char smem[];
    const uint32_t sb = smem_u32(smem);
    float* scale_s  = (float*)(smem + SM_SCL);
    float* bias_s   = (float*)(smem + SM_BIAS);
    float* ascale_s = (float*)(smem + SM_ASC);

    const int tid  = threadIdx.x;
    const int lane = tid & 31;
    const int wid  = tid >> 5;
    const int warp_m = wid >> 1;           // 0..3 -> 32 rows
    const int warp_n = wid & 1;            // 0..1 -> 64 cols
    const int m0 = blockIdx.y * BM;
    const int n0 = blockIdx.x * BN;

    // stage bias / activation row scales / first group's weight scales
    if (tid < 128) {
        bias_s[tid]   = bias[n0 + tid];
        ascale_s[tid] = ascale[(m0 + tid) & (SEQ - 1)];
        scale_s[tid]  = g_wsT[0 * N_TOTAL + n0 + tid];   // group 0 -> buf 0
    }

    // ---- global->smem addressing: 128 rows x 8 chunks(16B); 256 thr -> 4 iters
    const int ld_row = tid >> 3;           // 0..31 (+32/iter)
    const int ld_ch  = tid & 7;
    const int8_t* Agp = g_xq + (size_t)(m0 + ld_row) * K_TOTAL + ld_ch * 16;
    const int8_t* Bgp = g_w  + (size_t)(n0 + ld_row) * K_TOTAL + ld_ch * 16;
    const uint32_t ld_soff = swz((ld_row << 7) + (ld_ch << 4));

    // ---- ldmatrix lane addressing (s8 m16n8k32 fragments, 128B rows)
    const int a_row  = warp_m * 32 + (lane & 7) + ((lane >> 3) & 1) * 8;
    const int a_kofb = ((lane >> 4) & 1) * 16;
    const int b_row  = warp_n * 64 + (lane & 7) + ((lane >> 4) & 1) * 8;
    const int b_kofb = ((lane >> 3) & 1) * 16;

    float c[2][8][4];
    int  ci[2][8][4];
#pragma unroll
    for (int mt = 0; mt < 2; mt++)
#pragma unroll
        for (int nt = 0; nt < 8; nt++)
#pragma unroll
            for (int j = 0; j < 4; j++) { c[mt][nt][j] = 0.f; ci[mt][nt][j] = 0; }

    auto load_stage = [&](int kt, int stage) {
        uint32_t sa  = sb + stage * STAGE_BYTES + ld_soff;
        uint32_t sbB = sa + TILE_BYTES;
        const int8_t* ag = Agp + kt * BK;
        const int8_t* bg = Bgp + kt * BK;
#pragma unroll
        for (int it = 0; it < 4; it++) {
            CP_ASYNC_16(sa  + it * (32 << 7), ag + (size_t)(it * 32) * K_TOTAL);
            CP_ASYNC_16(sbB + it * (32 << 7), bg + (size_t)(it * 32) * K_TOTAL);
        }
    };

#pragma unroll
    for (int s = 0; s < STAGES - 1; s++) {
        load_stage(s, s);
        CP_ASYNC_COMMIT();
    }

    const int col_lo = warp_n * 64 + (lane & 3) * 2;   // local col of frag elems {0,1}
    const int row_lo = warp_m * 32 + (lane >> 2);      // local row of frag rows {0,8}

    int comp_stage = 0, next_stage = STAGES - 1;

    for (int kt = 0; kt < NT; kt++) {
        CP_ASYNC_WAIT(STAGES - 2);
        __syncthreads();

        if (kt + STAGES - 1 < NT)
            load_stage(kt + STAGES - 1, next_stage);
        CP_ASYNC_COMMIT();
        if (++next_stage == STAGES) next_stage = 0;

        // prefetch next group's weight scales into the other buffer
        if (kt + 1 < NT && tid < 128)
            scale_s[((kt + 1) & 1) * 128 + tid] = g_wsT[(kt + 1) * N_TOTAL + n0 + tid];

        const uint32_t Abase = sb + comp_stage * STAGE_BYTES;
        const uint32_t Bbase = Abase + TILE_BYTES;
        if (++comp_stage == STAGES) comp_stage = 0;

#pragma unroll
        for (int ks = 0; ks < 4; ks++) {
            uint32_t a[2][4];
#pragma unroll
            for (int mt = 0; mt < 2; mt++) {
                uint32_t addr = Abase + swz((uint32_t)(a_row + mt * 16) * BK + ks * 32 + a_kofb);
                ldmatrix_x4(a[mt][0], a[mt][1], a[mt][2], a[mt][3], addr);
            }
            uint32_t b[8][2];
#pragma unroll
            for (int np = 0; np < 4; np++) {
                uint32_t addr = Bbase + swz((uint32_t)(b_row + np * 16) * BK + ks * 32 + b_kofb);
                uint32_t r0, r1, r2, r3;
                ldmatrix_x4(r0, r1, r2, r3, addr);
                b[2 * np][0] = r0;     b[2 * np][1] = r1;
                b[2 * np + 1][0] = r2; b[2 * np + 1][1] = r3;
            }
#pragma unroll
            for (int mt = 0; mt < 2; mt++)
#pragma unroll
                for (int nt = 0; nt < 8; nt++)
                    mma_s8(ci[mt][nt][0], ci[mt][nt][1], ci[mt][nt][2], ci[mt][nt][3],
                           a[mt][0], a[mt][1], a[mt][2], a[mt][3],
                           b[nt][0], b[nt][1]);
        }

        __syncthreads();   // protects scale_s double-buffer + smem tile reuse

        // per-group fp32 rescale: c += scale[col] * (float)ci ; ci = 0
        const float* scl = scale_s + (kt & 1) * 128;
#pragma unroll
        for (int nt = 0; nt < 8; nt++) {
            float2 sc = *(const float2*)(scl + col_lo + nt * 8);
#pragma unroll
            for (int mt = 0; mt < 2; mt++) {
                c[mt][nt][0] = fmaf(sc.x, __int2float_rn(ci[mt][nt][0]), c[mt][nt][0]);
                c[mt][nt][1] = fmaf(sc.y, __int2float_rn(ci[mt][nt][1]), c[mt][nt][1]);
                c[mt][nt][2] = fmaf(sc.x, __int2float_rn(ci[mt][nt][2]), c[mt][nt][2]);
                c[mt][nt][3] = fmaf(sc.y, __int2float_rn(ci[mt][nt][3]), c[mt][nt][3]);
                ci[mt][nt][0] = 0; ci[mt][nt][1] = 0; ci[mt][nt][2] = 0; ci[mt][nt][3] = 0;
            }
        }
    }

    // ---- epilogue: out = c * s_row + bias
    const float s0  = ascale_s[row_lo];
    const float s8v = ascale_s[row_lo + 8];
    const float s16 = ascale_s[row_lo + 16];
    const float s24 = ascale_s[row_lo + 24];
#pragma unroll
    for (int nt = 0; nt < 8; nt++) {
        const int col = n0 + col_lo + nt * 8;
        const float2 bv = *(const float2*)(bias_s + col_lo + nt * 8);
#pragma unroll
        for (int mt = 0; mt < 2; mt++) {
            const int r0 = m0 + row_lo + mt * 16;
            const float sr0 = mt ? s16 : s0;
            const float sr8 = mt ? s24 : s8v;
            float2 v0 = make_float2(fmaf(c[mt][nt][0], sr0, bv.x), fmaf(c[mt][nt][1], sr0, bv.y));
            float2 v1 = make_float2(fmaf(c[mt][nt][2], sr8, bv.x), fmaf(c[mt][nt][3], sr8, bv.y));
            *(float2*)(out + (size_t)r0 * N_TOTAL + col) = v0;
            *(float2*)(out + (size_t)(r0 + 8) * N_TOTAL + col) = v1;
        }
    }
}

// ============================================================
// launch
// ============================================================
extern "C" void kernel_launch(void* const* d_in, const int* in_sizes, int n_in,
                              void* d_out, int out_size) {
    const float* x       = (const float*)d_in[0];   // (4, 2048, 4096) f32
    const int*   qweight = (const int*)d_in[1];     // (4096, 2048) i32
    const float* ascale  = (const float*)d_in[2];   // (1, 2048, 1) f32
    const float* wscale  = (const float*)d_in[3];   // (4096, 32) f32
    const int*   wzero   = (const int*)d_in[4];     // (4096, 32) i32
    const float* bias    = (const float*)d_in[5];   // (4096,) f32
    float* out = (float*)d_out;                     // (4, 2048, 4096) f32

    cudaFuncSetAttribute(gemm_kernel, cudaFuncAttributeMaxDynamicSharedMemorySize, SM_TOTAL);

    quant_x_kernel<<<(M_TOTAL * K_TOTAL / 4) / 256, 256>>>(x, ascale);
    prep_w_kernel<<<(N_TOTAL * (K_TOTAL / 2) / 4) / 256, 256>>>(qweight, wzero);
    transpose_ws_kernel<<<(N_TOTAL * NGRP) / 256, 256>>>(wscale);
    gemm_kernel<<<dim3(N_TOTAL / BN, M_TOTAL / BM), 256, SM_TOTAL>>>(bias, ascale, out);
}

// round 7
// speedup vs baseline: 1.4032x; 1.0790x over previous
#include <cuda_runtime.h>
#include <cuda_fp16.h>
#include <cstdint>

// ============================================================
// out[B*S, O] = fakequant(x) @ dequant(W)^T + bias
// M=8192, N=4096, K=4096, group G=128 (NGRP=32 groups)
// Exact-int8: q_x s8, w centered s8; IMMA m16n8k32; fp32 group rescale.
// Plain sm_100 target -> mma.sync + ldmatrix + cp.async.
// ============================================================
#define M_TOTAL 8192
#define N_TOTAL 4096
#define K_TOTAL 4096
#define SEQ     2048
#define NGRP    32

__device__ __align__(256) int8_t g_xq  [(size_t)M_TOTAL * K_TOTAL];
__device__ __align__(256) int8_t g_w   [(size_t)N_TOTAL * K_TOTAL];
__device__ __align__(256) float  g_wsT [NGRP * N_TOTAL];

__device__ __forceinline__ uint32_t smem_u32(const void* p) {
    uint32_t a;
    asm("{ .reg .u64 t; cvta.to.shared.u64 t, %1; cvt.u32.u64 %0, t; }" : "=r"(a) : "l"(p));
    return a;
}

#define CP_ASYNC_16(dst, src) \
    asm volatile("cp.async.cg.shared.global.L2::128B [%0], [%1], 16;" \
                 :: "r"(dst), "l"(src) : "memory")
#define CP_ASYNC_COMMIT() asm volatile("cp.async.commit_group;" ::: "memory")
#define CP_ASYNC_WAIT(n)  asm volatile("cp.async.wait_group %0;" :: "n"(n) : "memory")

__device__ __forceinline__ void ldmatrix_x4(uint32_t& r0, uint32_t& r1,
                                            uint32_t& r2, uint32_t& r3, uint32_t addr) {
    asm volatile("ldmatrix.sync.aligned.m8n8.x4.shared.b16 {%0,%1,%2,%3}, [%4];"
                 : "=r"(r0), "=r"(r1), "=r"(r2), "=r"(r3) : "r"(addr));
}

// accumulate form
__device__ __forceinline__ void mma_s8(int& c0, int& c1, int& c2, int& c3,
                                       uint32_t a0, uint32_t a1, uint32_t a2, uint32_t a3,
                                       uint32_t b0, uint32_t b1) {
    asm volatile(
        "mma.sync.aligned.m16n8k32.row.col.s32.s8.s8.s32 "
        "{%0,%1,%2,%3}, {%4,%5,%6,%7}, {%8,%9}, {%0,%1,%2,%3};"
        : "+r"(c0), "+r"(c1), "+r"(c2), "+r"(c3)
        : "r"(a0), "r"(a1), "r"(a2), "r"(a3), "r"(b0), "r"(b1));
}

// write form: C_in = 0 (kills the per-group zeroing MOVs, breaks the
// cross-group register dependency on ci)
__device__ __forceinline__ void mma_s8_init(int& c0, int& c1, int& c2, int& c3,
                                            uint32_t a0, uint32_t a1, uint32_t a2, uint32_t a3,
                                            uint32_t b0, uint32_t b1) {
    asm volatile(
        "mma.sync.aligned.m16n8k32.row.col.s32.s8.s8.s32 "
        "{%0,%1,%2,%3}, {%4,%5,%6,%7}, {%8,%9}, {%10,%10,%10,%10};"
        : "=r"(c0), "=r"(c1), "=r"(c2), "=r"(c3)
        : "r"(a0), "r"(a1), "r"(a2), "r"(a3), "r"(b0), "r"(b1), "r"(0));
}

// ============================================================
// Kernel 1: activation quant -> s8 (rintf = round-half-even = jnp.round)
// ============================================================
__global__ void __launch_bounds__(256) quant_x_kernel(const float* __restrict__ x,
                                                      const float* __restrict__ ascale) {
    int idx = blockIdx.x * 256 + threadIdx.x;              // one float4 -> 4 s8
    float4 v = ((const float4*)x)[idx];
    float s = ascale[(idx >> 10) & (SEQ - 1)];
    int qa = (int)fminf(fmaxf(rintf(__fdiv_rn(v.x, s)), -127.f), 127.f);
    int qb = (int)fminf(fmaxf(rintf(__fdiv_rn(v.y, s)), -127.f), 127.f);
    int qc = (int)fminf(fmaxf(rintf(__fdiv_rn(v.z, s)), -127.f), 127.f);
    int qd = (int)fminf(fmaxf(rintf(__fdiv_rn(v.w, s)), -127.f), 127.f);
    uint32_t packed = (qa & 0xFF) | ((qb & 0xFF) << 8) | ((qc & 0xFF) << 16) | ((qd & 0xFF) << 24);
    ((uint32_t*)g_xq)[idx] = packed;
}

// ============================================================
// Kernel 2: weight unpack + center -> s8, K-major [O][K]
// ============================================================
__global__ void __launch_bounds__(256) prep_w_kernel(const int* __restrict__ qw,
                                                     const int* __restrict__ wz) {
    int idx = blockIdx.x * 256 + threadIdx.x;  // 4 int32 -> 8 s8
    int4 q = ((const int4*)qw)[idx];
    int j0 = idx << 2;
    int o = j0 >> 11;
    int g = (j0 & 2047) >> 6;
    int z = wz[o * NGRP + g];
    int qs[4] = {q.x, q.y, q.z, q.w};
    uint32_t out2[2];
    uint8_t* ob = (uint8_t*)out2;
#pragma unroll
    for (int t = 0; t < 4; t++) {
        int lo = (qs[t] & 15) - z;
        int hi = ((qs[t] >> 4) & 15) - z;
        ob[2 * t]     = (uint8_t)(int8_t)lo;
        ob[2 * t + 1] = (uint8_t)(int8_t)hi;
    }
    ((uint2*)g_w)[idx] = make_uint2(out2[0], out2[1]);
}

// ============================================================
// Kernel 3: transpose weight_scale [O][NGRP] -> [NGRP][O]
// ============================================================
__global__ void __launch_bounds__(256) transpose_ws_kernel(const float* __restrict__ ws) {
    int idx = blockIdx.x * 256 + threadIdx.x;
    int o = idx >> 5, g = idx & 31;
    g_wsT[g * N_TOTAL + o] = ws[idx];
}

// ============================================================
// Kernel 4: IMMA GEMM. Block 128x128, BK=128 (= one group), 4-stage
// cp.async, 8 warps (4M x 2N), m16n8k32.s8, ONE barrier per k-tile.
// ============================================================
#define BM 128
#define BN 128
#define BK 128
#define STAGES 4
#define NT (K_TOTAL / BK)          // 32

#define TILE_BYTES (BM * BK)       // 16384 (int8)
#define STAGE_BYTES (2 * TILE_BYTES)
#define SM_MAIN  (STAGES * STAGE_BYTES)      // 128 KB
#define SM_SCL   SM_MAIN                     // scale_s[2][128]
#define SM_BIAS  (SM_SCL + 2 * 128 * 4)
#define SM_ASC   (SM_BIAS + 128 * 4)
#define SM_TOTAL (SM_ASC + 128 * 4)

__device__ __forceinline__ uint32_t swz(uint32_t off) {
    return off ^ ((off >> 3) & 0x70);
}

__global__ void __launch_bounds__(256, 1) gemm_kernel(const float* __restrict__ bias,
                                                      const float* __restrict__ ascale,
                                                      float* __restrict__ out) {
    extern __shared__ char smem[];
    const uint32_t sb = smem_u32(smem);
    float* scale_s  = (float*)(smem + SM_SCL);
    float* bias_s   = (float*)(smem + SM_BIAS);
    float* ascale_s = (float*)(smem + SM_ASC);

    const int tid  = threadIdx.x;
    const int lane = tid & 31;
    const int wid  = tid >> 5;
    const int warp_m = wid >> 1;
    const int warp_n = wid & 1;
    const int m0 = blockIdx.y * BM;
    const int n0 = blockIdx.x * BN;

    if (tid < 128) {
        bias_s[tid]   = bias[n0 + tid];
        ascale_s[tid] = ascale[(m0 + tid) & (SEQ - 1)];
        scale_s[tid]  = g_wsT[0 * N_TOTAL + n0 + tid];   // group 0 -> buf 0
    }

    const int ld_row = tid >> 3;
    const int ld_ch  = tid & 7;
    const int8_t* Agp = g_xq + (size_t)(m0 + ld_row) * K_TOTAL + ld_ch * 16;
    const int8_t* Bgp = g_w  + (size_t)(n0 + ld_row) * K_TOTAL + ld_ch * 16;
    const uint32_t ld_soff = swz((ld_row << 7) + (ld_ch << 4));

    const int a_row  = warp_m * 32 + (lane & 7) + ((lane >> 3) & 1) * 8;
    const int a_kofb = ((lane >> 4) & 1) * 16;
    const int b_row  = warp_n * 64 + (lane & 7) + ((lane >> 4) & 1) * 8;
    const int b_kofb = ((lane >> 3) & 1) * 16;

    float c[2][8][4];
    int  ci[2][8][4];
#pragma unroll
    for (int mt = 0; mt < 2; mt++)
#pragma unroll
        for (int nt = 0; nt < 8; nt++)
#pragma unroll
            for (int j = 0; j < 4; j++) c[mt][nt][j] = 0.f;

    auto load_stage = [&](int kt, int stage) {
        uint32_t sa  = sb + stage * STAGE_BYTES + ld_soff;
        uint32_t sbB = sa + TILE_BYTES;
        const int8_t* ag = Agp + kt * BK;
        const int8_t* bg = Bgp + kt * BK;
#pragma unroll
        for (int it = 0; it < 4; it++) {
            CP_ASYNC_16(sa  + it * (32 << 7), ag + (size_t)(it * 32) * K_TOTAL);
            CP_ASYNC_16(sbB + it * (32 << 7), bg + (size_t)(it * 32) * K_TOTAL);
        }
    };

#pragma unroll
    for (int s = 0; s < STAGES - 1; s++) {
        load_stage(s, s);
        CP_ASYNC_COMMIT();
    }

    const int col_lo = warp_n * 64 + (lane & 3) * 2;
    const int row_lo = warp_m * 32 + (lane >> 2);

    int comp_stage = 0, next_stage = STAGES - 1;

    for (int kt = 0; kt < NT; kt++) {
        CP_ASYNC_WAIT(STAGES - 2);
        __syncthreads();   // single barrier per k-tile: orders stage reuse,
                           // scale_s double-buffer, and cp.async visibility

        if (kt + STAGES - 1 < NT)
            load_stage(kt + STAGES - 1, next_stage);
        CP_ASYNC_COMMIT();
        if (++next_stage == STAGES) next_stage = 0;

        if (kt + 1 < NT && tid < 128)
            scale_s[((kt + 1) & 1) * 128 + tid] = g_wsT[(kt + 1) * N_TOTAL + n0 + tid];

        const uint32_t Abase = sb + comp_stage * STAGE_BYTES;
        const uint32_t Bbase = Abase + TILE_BYTES;
        if (++comp_stage == STAGES) comp_stage = 0;

#pragma unroll
        for (int ks = 0; ks < 4; ks++) {
            uint32_t a[2][4];
#pragma unroll
            for (int mt = 0; mt < 2; mt++) {
                uint32_t addr = Abase + swz((uint32_t)(a_row + mt * 16) * BK + ks * 32 + a_kofb);
                ldmatrix_x4(a[mt][0], a[mt][1], a[mt][2], a[mt][3], addr);
            }
            uint32_t b[8][2];
#pragma unroll
            for (int np = 0; np < 4; np++) {
                uint32_t addr = Bbase + swz((uint32_t)(b_row + np * 16) * BK + ks * 32 + b_kofb);
                uint32_t r0, r1, r2, r3;
                ldmatrix_x4(r0, r1, r2, r3, addr);
                b[2 * np][0] = r0;     b[2 * np][1] = r1;
                b[2 * np + 1][0] = r2; b[2 * np + 1][1] = r3;
            }
            if (ks == 0) {
#pragma unroll
                for (int mt = 0; mt < 2; mt++)
#pragma unroll
                    for (int nt = 0; nt < 8; nt++)
                        mma_s8_init(ci[mt][nt][0], ci[mt][nt][1], ci[mt][nt][2], ci[mt][nt][3],
                                    a[mt][0], a[mt][1], a[mt][2], a[mt][3],
                                    b[nt][0], b[nt][1]);
            } else {
#pragma unroll
                for (int mt = 0; mt < 2; mt++)
#pragma unroll
                    for (int nt = 0; nt < 8; nt++)
                        mma_s8(ci[mt][nt][0], ci[mt][nt][1], ci[mt][nt][2], ci[mt][nt][3],
                               a[mt][0], a[mt][1], a[mt][2], a[mt][3],
                               b[nt][0], b[nt][1]);
            }
        }

        // per-group fp32 rescale (no barrier: next-iter barrier orders hazards)
        const float* scl = scale_s + (kt & 1) * 128;
#pragma unroll
        for (int nt = 0; nt < 8; nt++) {
            float2 sc = *(const float2*)(scl + col_lo + nt * 8);
#pragma unroll
            for (int mt = 0; mt < 2; mt++) {
                c[mt][nt][0] = fmaf(sc.x, __int2float_rn(ci[mt][nt][0]), c[mt][nt][0]);
                c[mt][nt][1] = fmaf(sc.y, __int2float_rn(ci[mt][nt][1]), c[mt][nt][1]);
                c[mt][nt][2] = fmaf(sc.x, __int2float_rn(ci[mt][nt][2]), c[mt][nt][2]);
                c[mt][nt][3] = fmaf(sc.y, __int2float_rn(ci[mt][nt][3]), c[mt][nt][3]);
            }
        }
    }

    // ---- epilogue: out = c * s_row + bias
    const float s0  = ascale_s[row_lo];
    const float s8v = ascale_s[row_lo + 8];
    const float s16 = ascale_s[row_lo + 16];
    const float s24 = ascale_s[row_lo + 24];
#pragma unroll
    for (int nt = 0; nt < 8; nt++) {
        const int col = n0 + col_lo + nt * 8;
        const float2 bv = *(const float2*)(bias_s + col_lo + nt * 8);
#pragma unroll
        for (int mt = 0; mt < 2; mt++) {
            const int r0 = m0 + row_lo + mt * 16;
            const float sr0 = mt ? s16 : s0;
            const float sr8 = mt ? s24 : s8v;
            float2 v0 = make_float2(fmaf(c[mt][nt][0], sr0, bv.x), fmaf(c[mt][nt][1], sr0, bv.y));
            float2 v1 = make_float2(fmaf(c[mt][nt][2], sr8, bv.x), fmaf(c[mt][nt][3], sr8, bv.y));
            *(float2*)(out + (size_t)r0 * N_TOTAL + col) = v0;
            *(float2*)(out + (size_t)(r0 + 8) * N_TOTAL + col) = v1;
        }
    }
}

// ============================================================
// launch
// ============================================================
extern "C" void kernel_launch(void* const* d_in, const int* in_sizes, int n_in,
                              void* d_out, int out_size) {
    const float* x       = (const float*)d_in[0];
    const int*   qweight = (const int*)d_in[1];
    const float* ascale  = (const float*)d_in[2];
    const float* wscale  = (const float*)d_in[3];
    const int*   wzero   = (const int*)d_in[4];
    const float* bias    = (const float*)d_in[5];
    float* out = (float*)d_out;

    cudaFuncSetAttribute(gemm_kernel, cudaFuncAttributeMaxDynamicSharedMemorySize, SM_TOTAL);

    quant_x_kernel<<<(M_TOTAL * K_TOTAL / 4) / 256, 256>>>(x, ascale);
    prep_w_kernel<<<(N_TOTAL * (K_TOTAL / 2) / 4) / 256, 256>>>(qweight, wzero);
    transpose_ws_kernel<<<(N_TOTAL * NGRP) / 256, 256>>>(wscale);
    gemm_kernel<<<dim3(N_TOTAL / BN, M_TOTAL / BM), 256, SM_TOTAL>>>(bias, ascale, out);
}

// round 8
// speedup vs baseline: 1.5485x; 1.1036x over previous
#include <cuda_runtime.h>
#include <cuda_fp16.h>
#include <cstdint>

// ============================================================
// out[B*S, O] = fakequant(x) @ dequant(W)^T + bias
// M=8192, N=4096, K=4096, group G=128 (NGRP=32 groups)
// Exact-int8: q_x s8, w centered s8; IMMA m16n8k32; fp32 group rescale.
// Plain sm_100 target -> mma.sync + ldmatrix + cp.async.
// R8: 512 threads/CTA (16 warps, 4Mx4N), warp tile 32x32 ->
//     4 warps/SMSP for latency hiding (was 2).
// ============================================================
#define M_TOTAL 8192
#define N_TOTAL 4096
#define K_TOTAL 4096
#define SEQ     2048
#define NGRP    32

__device__ __align__(256) int8_t g_xq  [(size_t)M_TOTAL * K_TOTAL];
__device__ __align__(256) int8_t g_w   [(size_t)N_TOTAL * K_TOTAL];
__device__ __align__(256) float  g_wsT [NGRP * N_TOTAL];

__device__ __forceinline__ uint32_t smem_u32(const void* p) {
    uint32_t a;
    asm("{ .reg .u64 t; cvta.to.shared.u64 t, %1; cvt.u32.u64 %0, t; }" : "=r"(a) : "l"(p));
    return a;
}

#define CP_ASYNC_16(dst, src) \
    asm volatile("cp.async.cg.shared.global.L2::128B [%0], [%1], 16;" \
                 :: "r"(dst), "l"(src) : "memory")
#define CP_ASYNC_COMMIT() asm volatile("cp.async.commit_group;" ::: "memory")
#define CP_ASYNC_WAIT(n)  asm volatile("cp.async.wait_group %0;" :: "n"(n) : "memory")

__device__ __forceinline__ void ldmatrix_x4(uint32_t& r0, uint32_t& r1,
                                            uint32_t& r2, uint32_t& r3, uint32_t addr) {
    asm volatile("ldmatrix.sync.aligned.m8n8.x4.shared.b16 {%0,%1,%2,%3}, [%4];"
                 : "=r"(r0), "=r"(r1), "=r"(r2), "=r"(r3) : "r"(addr));
}

__device__ __forceinline__ void mma_s8(int& c0, int& c1, int& c2, int& c3,
                                       uint32_t a0, uint32_t a1, uint32_t a2, uint32_t a3,
                                       uint32_t b0, uint32_t b1) {
    asm volatile(
        "mma.sync.aligned.m16n8k32.row.col.s32.s8.s8.s32 "
        "{%0,%1,%2,%3}, {%4,%5,%6,%7}, {%8,%9}, {%0,%1,%2,%3};"
        : "+r"(c0), "+r"(c1), "+r"(c2), "+r"(c3)
        : "r"(a0), "r"(a1), "r"(a2), "r"(a3), "r"(b0), "r"(b1));
}

__device__ __forceinline__ void mma_s8_init(int& c0, int& c1, int& c2, int& c3,
                                            uint32_t a0, uint32_t a1, uint32_t a2, uint32_t a3,
                                            uint32_t b0, uint32_t b1) {
    asm volatile(
        "mma.sync.aligned.m16n8k32.row.col.s32.s8.s8.s32 "
        "{%0,%1,%2,%3}, {%4,%5,%6,%7}, {%8,%9}, {%10,%10,%10,%10};"
        : "=r"(c0), "=r"(c1), "=r"(c2), "=r"(c3)
        : "r"(a0), "r"(a1), "r"(a2), "r"(a3), "r"(b0), "r"(b1), "r"(0));
}

// ============================================================
// Kernel 1: activation quant -> s8 (rintf = round-half-even = jnp.round)
// ============================================================
__global__ void __launch_bounds__(256) quant_x_kernel(const float* __restrict__ x,
                                                      const float* __restrict__ ascale) {
    int idx = blockIdx.x * 256 + threadIdx.x;
    float4 v = ((const float4*)x)[idx];
    float s = ascale[(idx >> 10) & (SEQ - 1)];
    int qa = (int)fminf(fmaxf(rintf(__fdiv_rn(v.x, s)), -127.f), 127.f);
    int qb = (int)fminf(fmaxf(rintf(__fdiv_rn(v.y, s)), -127.f), 127.f);
    int qc = (int)fminf(fmaxf(rintf(__fdiv_rn(v.z, s)), -127.f), 127.f);
    int qd = (int)fminf(fmaxf(rintf(__fdiv_rn(v.w, s)), -127.f), 127.f);
    uint32_t packed = (qa & 0xFF) | ((qb & 0xFF) << 8) | ((qc & 0xFF) << 16) | ((qd & 0xFF) << 24);
    ((uint32_t*)g_xq)[idx] = packed;
}

// ============================================================
// Kernel 2: weight unpack + center -> s8, K-major [O][K]
// ============================================================
__global__ void __launch_bounds__(256) prep_w_kernel(const int* __restrict__ qw,
                                                     const int* __restrict__ wz) {
    int idx = blockIdx.x * 256 + threadIdx.x;
    int4 q = ((const int4*)qw)[idx];
    int j0 = idx << 2;
    int o = j0 >> 11;
    int g = (j0 & 2047) >> 6;
    int z = wz[o * NGRP + g];
    int qs[4] = {q.x, q.y, q.z, q.w};
    uint32_t out2[2];
    uint8_t* ob = (uint8_t*)out2;
#pragma unroll
    for (int t = 0; t < 4; t++) {
        int lo = (qs[t] & 15) - z;
        int hi = ((qs[t] >> 4) & 15) - z;
        ob[2 * t]     = (uint8_t)(int8_t)lo;
        ob[2 * t + 1] = (uint8_t)(int8_t)hi;
    }
    ((uint2*)g_w)[idx] = make_uint2(out2[0], out2[1]);
}

// ============================================================
// Kernel 3: transpose weight_scale [O][NGRP] -> [NGRP][O]
// ============================================================
__global__ void __launch_bounds__(256) transpose_ws_kernel(const float* __restrict__ ws) {
    int idx = blockIdx.x * 256 + threadIdx.x;
    int o = idx >> 5, g = idx & 31;
    g_wsT[g * N_TOTAL + o] = ws[idx];
}

// ============================================================
// Kernel 4: IMMA GEMM. Block 128x128, BK=128, 4-stage cp.async,
// 16 warps (4M x 4N), warp tile 32x32, m16n8k32.s8.
// ============================================================
#define BM 128
#define BN 128
#define BK 128
#define STAGES 4
#define NT (K_TOTAL / BK)          // 32
#define NTHREADS 512

#define TILE_BYTES (BM * BK)       // 16384
#define STAGE_BYTES (2 * TILE_BYTES)
#define SM_MAIN  (STAGES * STAGE_BYTES)      // 128 KB
#define SM_SCL   SM_MAIN
#define SM_BIAS  (SM_SCL + 2 * 128 * 4)
#define SM_ASC   (SM_BIAS + 128 * 4)
#define SM_TOTAL (SM_ASC + 128 * 4)

__device__ __forceinline__ uint32_t swz(uint32_t off) {
    return off ^ ((off >> 3) & 0x70);
}

__global__ void __launch_bounds__(NTHREADS, 1) gemm_kernel(const float* __restrict__ bias,
                                                           const float* __restrict__ ascale,
                                                           float* __restrict__ out) {
    extern __shared__ char smem[];
    const uint32_t sb = smem_u32(smem);
    float* scale_s  = (float*)(smem + SM_SCL);
    float* bias_s   = (float*)(smem + SM_BIAS);
    float* ascale_s = (float*)(smem + SM_ASC);

    const int tid  = threadIdx.x;
    const int lane = tid & 31;
    const int wid  = tid >> 5;
    const int warp_m = wid >> 2;           // 0..3 -> 32 rows
    const int warp_n = wid & 3;            // 0..3 -> 32 cols
    const int m0 = blockIdx.y * BM;
    const int n0 = blockIdx.x * BN;

    if (tid < 128) {
        bias_s[tid]   = bias[n0 + tid];
        ascale_s[tid] = ascale[(m0 + tid) & (SEQ - 1)];
        scale_s[tid]  = g_wsT[0 * N_TOTAL + n0 + tid];   // group 0 -> buf 0
    }

    // ---- global->smem: 128 rows x 8 chunks(16B) per tile; 512 thr -> 2 iters
    const int ld_row = tid >> 3;           // 0..63 (+64/iter)
    const int ld_ch  = tid & 7;
    const int8_t* Agp = g_xq + (size_t)(m0 + ld_row) * K_TOTAL + ld_ch * 16;
    const int8_t* Bgp = g_w  + (size_t)(n0 + ld_row) * K_TOTAL + ld_ch * 16;
    const uint32_t ld_soff = swz((ld_row << 7) + (ld_ch << 4));

    // ---- ldmatrix lane addressing
    const int a_row  = warp_m * 32 + (lane & 7) + ((lane >> 3) & 1) * 8;
    const int a_kofb = ((lane >> 4) & 1) * 16;
    const int b_row  = warp_n * 32 + (lane & 7) + ((lane >> 4) & 1) * 8;
    const int b_kofb = ((lane >> 3) & 1) * 16;

    float c[2][4][4];
    int  ci[2][4][4];
#pragma unroll
    for (int mt = 0; mt < 2; mt++)
#pragma unroll
        for (int nt = 0; nt < 4; nt++)
#pragma unroll
            for (int j = 0; j < 4; j++) c[mt][nt][j] = 0.f;

    auto load_stage = [&](int kt, int stage) {
        uint32_t sa  = sb + stage * STAGE_BYTES + ld_soff;
        uint32_t sbB = sa + TILE_BYTES;
        const int8_t* ag = Agp + kt * BK;
        const int8_t* bg = Bgp + kt * BK;
#pragma unroll
        for (int it = 0; it < 2; it++) {
            CP_ASYNC_16(sa  + it * (64 << 7), ag + (size_t)(it * 64) * K_TOTAL);
            CP_ASYNC_16(sbB + it * (64 << 7), bg + (size_t)(it * 64) * K_TOTAL);
        }
    };

#pragma unroll
    for (int s = 0; s < STAGES - 1; s++) {
        load_stage(s, s);
        CP_ASYNC_COMMIT();
    }

    const int col_lo = warp_n * 32 + (lane & 3) * 2;
    const int row_lo = warp_m * 32 + (lane >> 2);

    int comp_stage = 0, next_stage = STAGES - 1;

    for (int kt = 0; kt < NT; kt++) {
        CP_ASYNC_WAIT(STAGES - 2);
        __syncthreads();   // single barrier per k-tile

        if (kt + STAGES - 1 < NT)
            load_stage(kt + STAGES - 1, next_stage);
        CP_ASYNC_COMMIT();
        if (++next_stage == STAGES) next_stage = 0;

        if (kt + 1 < NT && tid < 128)
            scale_s[((kt + 1) & 1) * 128 + tid] = g_wsT[(kt + 1) * N_TOTAL + n0 + tid];

        const uint32_t Abase = sb + comp_stage * STAGE_BYTES;
        const uint32_t Bbase = Abase + TILE_BYTES;
        if (++comp_stage == STAGES) comp_stage = 0;

#pragma unroll
        for (int ks = 0; ks < 4; ks++) {
            uint32_t a[2][4];
#pragma unroll
            for (int mt = 0; mt < 2; mt++) {
                uint32_t addr = Abase + swz((uint32_t)(a_row + mt * 16) * BK + ks * 32 + a_kofb);
                ldmatrix_x4(a[mt][0], a[mt][1], a[mt][2], a[mt][3], addr);
            }
            uint32_t b[4][2];
#pragma unroll
            for (int np = 0; np < 2; np++) {
                uint32_t addr = Bbase + swz((uint32_t)(b_row + np * 16) * BK + ks * 32 + b_kofb);
                uint32_t r0, r1, r2, r3;
                ldmatrix_x4(r0, r1, r2, r3, addr);
                b[2 * np][0] = r0;     b[2 * np][1] = r1;
                b[2 * np + 1][0] = r2; b[2 * np + 1][1] = r3;
            }
            if (ks == 0) {
#pragma unroll
                for (int mt = 0; mt < 2; mt++)
#pragma unroll
                    for (int nt = 0; nt < 4; nt++)
                        mma_s8_init(ci[mt][nt][0], ci[mt][nt][1], ci[mt][nt][2], ci[mt][nt][3],
                                    a[mt][0], a[mt][1], a[mt][2], a[mt][3],
                                    b[nt][0], b[nt][1]);
            } else {
#pragma unroll
                for (int mt = 0; mt < 2; mt++)
#pragma unroll
                    for (int nt = 0; nt < 4; nt++)
                        mma_s8(ci[mt][nt][0], ci[mt][nt][1], ci[mt][nt][2], ci[mt][nt][3],
                               a[mt][0], a[mt][1], a[mt][2], a[mt][3],
                               b[nt][0], b[nt][1]);
            }
        }

        // per-group fp32 rescale (next-iter barrier orders the hazards)
        const float* scl = scale_s + (kt & 1) * 128;
#pragma unroll
        for (int nt = 0; nt < 4; nt++) {
            float2 sc = *(const float2*)(scl + col_lo + nt * 8);
#pragma unroll
            for (int mt = 0; mt < 2; mt++) {
                c[mt][nt][0] = fmaf(sc.x, __int2float_rn(ci[mt][nt][0]), c[mt][nt][0]);
                c[mt][nt][1] = fmaf(sc.y, __int2float_rn(ci[mt][nt][1]), c[mt][nt][1]);
                c[mt][nt][2] = fmaf(sc.x, __int2float_rn(ci[mt][nt][2]), c[mt][nt][2]);
                c[mt][nt][3] = fmaf(sc.y, __int2float_rn(ci[mt][nt][3]), c[mt][nt][3]);
            }
        }
    }

    // ---- epilogue: out = c * s_row + bias
    const float s0  = ascale_s[row_lo];
    const float s8v = ascale_s[row_lo + 8];
    const float s16 = ascale_s[row_lo + 16];
    const float s24 = ascale_s[row_lo + 24];
#pragma unroll
    for (int nt = 0; nt < 4; nt++) {
        const int col = n0 + col_lo + nt * 8;
        const float2 bv = *(const float2*)(bias_s + col_lo + nt * 8);
#pragma unroll
        for (int mt = 0; mt < 2; mt++) {
            const int r0 = m0 + row_lo + mt * 16;
            const float sr0 = mt ? s16 : s0;
            const float sr8 = mt ? s24 : s8v;
            float2 v0 = make_float2(fmaf(c[mt][nt][0], sr0, bv.x), fmaf(c[mt][nt][1], sr0, bv.y));
            float2 v1 = make_float2(fmaf(c[mt][nt][2], sr8, bv.x), fmaf(c[mt][nt][3], sr8, bv.y));
            *(float2*)(out + (size_t)r0 * N_TOTAL + col) = v0;
            *(float2*)(out + (size_t)(r0 + 8) * N_TOTAL + col) = v1;
        }
    }
}

// ============================================================
// launch
// ============================================================
extern "C" void kernel_launch(void* const* d_in, const int* in_sizes, int n_in,
                              void* d_out, int out_size) {
    const float* x       = (const float*)d_in[0];
    const int*   qweight = (const int*)d_in[1];
    const float* ascale  = (const float*)d_in[2];
    const float* wscale  = (const float*)d_in[3];
    const int*   wzero   = (const int*)d_in[4];
    const float* bias    = (const float*)d_in[5];
    float* out = (float*)d_out;

    cudaFuncSetAttribute(gemm_kernel, cudaFuncAttributeMaxDynamicSharedMemorySize, SM_TOTAL);

    quant_x_kernel<<<(M_TOTAL * K_TOTAL / 4) / 256, 256>>>(x, ascale);
    prep_w_kernel<<<(N_TOTAL * (K_TOTAL / 2) / 4) / 256, 256>>>(qweight, wzero);
    transpose_ws_kernel<<<(N_TOTAL * NGRP) / 256, 256>>>(wscale);
    gemm_kernel<<<dim3(N_TOTAL / BN, M_TOTAL / BM), NTHREADS, SM_TOTAL>>>(bias, ascale, out);
}